// round 16
// baseline (speedup 1.0000x reference)
#include <cuda_runtime.h>
#include <cstdint>

// ---------------- problem constants ----------------
#define USERN 100000
#define ITEMN 50000
#define TAGN  20000
#define NN (USERN + ITEMN)   // 150000 interaction-graph nodes
#define MM (ITEMN + TAGN)    // 70000 tag-graph nodes
#define RTOT (NN + MM + USERN)  // 320000 unified gather rows
#define DD 64
#define Q4 16                // float4 per embedding row
#define Q2 32                // float2 per embedding row
#define E_ADJ 2000000
#define E_TAG 1000000
#define E_SOC 1000000
#define E_TOT (E_ADJ + E_TAG + E_SOC)

// scan block counts (256 threads/block)
#define NBA ((NN + 255) / 256)      // 586
#define NBT ((MM + 255) / 256)      // 274
#define NBS ((USERN + 255) / 256)   // 391

// ---------------- device scratch (no allocs allowed) ----------------
__device__ float g_lat[NN * DD];
__device__ float g_taglat[MM * DD];
__device__ float g_tem[NN * DD];     // adj-graph row sums (gather output)
__device__ float g_tg[MM * DD];      // tag-graph row sums
__device__ float g_soc[USERN * DD];  // social-graph row sums

// CSR scratch (structure constant across layers; built once per call)
__device__ int g_cnt_adj[NN];
__device__ int g_off_adj[NN + 1];
__device__ int g_cur_adj[NN];
__device__ int g_cnt_tag[MM];
__device__ int g_off_tag[MM + 1];
__device__ int g_cur_tag[MM];
__device__ int g_cnt_soc[USERN];
__device__ int g_off_soc[USERN + 1];
__device__ int g_cur_soc[USERN];
__device__ int g_part[3][1024];      // block partials for the 3 scans
// Binned edge records: x=col, y=layer0 weight bits, z=layer1 weight bits, w=pad
__device__ int4 g_ce_adj[E_ADJ];
__device__ int4 g_ce_tag[E_TAG];
__device__ int4 g_ce_soc[E_SOC];

// ---------------- threefry-2x32 (exact JAX implementation) ----------------
__host__ __device__ __forceinline__ void tf2x32(uint32_t k0, uint32_t k1,
                                                uint32_t x0, uint32_t x1,
                                                uint32_t& o0, uint32_t& o1) {
    uint32_t ks2 = k0 ^ k1 ^ 0x1BD11BDAu;
    x0 += k0; x1 += k1;
#define TF_RR(r) { x0 += x1; x1 = (x1 << (r)) | (x1 >> (32 - (r))); x1 ^= x0; }
    TF_RR(13) TF_RR(15) TF_RR(26) TF_RR(6)   x0 += k1;  x1 += ks2 + 1u;
    TF_RR(17) TF_RR(29) TF_RR(16) TF_RR(24)  x0 += ks2; x1 += k0 + 2u;
    TF_RR(13) TF_RR(15) TF_RR(26) TF_RR(6)   x0 += k0;  x1 += k1 + 3u;
    TF_RR(17) TF_RR(29) TF_RR(16) TF_RR(24)  x0 += k1;  x1 += ks2 + 4u;
    TF_RR(13) TF_RR(15) TF_RR(26) TF_RR(6)   x0 += ks2; x1 += k0 + 5u;
#undef TF_RR
    o0 = x0; o1 = x1;
}

// Bit-exact JAX dropout weight (partitionable threefry: bits = xor-fold of
// threefry2x32(key, 0, e)); weight = val * floor(u + KEEP) / KEEP.
__device__ __forceinline__ float drop_weight(uint32_t k0, uint32_t k1,
                                             uint32_t e, float val) {
    uint32_t o0, o1;
    tf2x32(k0, k1, 0u, e, o0, o1);
    uint32_t bits = o0 ^ o1;
    float u = __uint_as_float((bits >> 9) | 0x3f800000u) - 1.0f;
    float m = floorf(u + 0.9f);
    return val * m * (float)(1.0 / 0.9);
}

// ---------------- init: embeddings + acc seed + CSR count zeroing ----------
__global__ void init_kernel(const float4* __restrict__ uE,
                            const float4* __restrict__ iE,
                            const float4* __restrict__ tE,
                            float4* __restrict__ out) {
    int t = blockIdx.x * blockDim.x + threadIdx.x;
    if (t < NN * Q4) {
        float4 v = (t < USERN * Q4) ? uE[t] : iE[t - USERN * Q4];
        reinterpret_cast<float4*>(g_lat)[t] = v;
        out[t] = v;                                    // acc starts at lat
    }
    if (t < MM * Q4) {
        float4 v = (t < ITEMN * Q4) ? iE[t] : tE[t - ITEMN * Q4];
        reinterpret_cast<float4*>(g_taglat)[t] = v;
    }
    if (t < NN) g_cnt_adj[t] = 0;
    if (t < MM) g_cnt_tag[t] = 0;
    if (t < USERN) g_cnt_soc[t] = 0;
}

// ---------------- CSR build (once per call) --------------------------------
__global__ void hist_all_kernel(const int* __restrict__ ar,
                                const int* __restrict__ tr,
                                const int* __restrict__ sr) {
    int t = blockIdx.x * blockDim.x + threadIdx.x;
    if (t < E_ADJ)              atomicAdd(g_cnt_adj + ar[t], 1);
    else if (t < E_ADJ + E_TAG) atomicAdd(g_cnt_tag + tr[t - E_ADJ], 1);
    else if (t < E_TOT)         atomicAdd(g_cnt_soc + sr[t - E_ADJ - E_TAG], 1);
}

// --- merged 3-pass parallel exclusive scan over all three graphs ---
__global__ void scanA_all_kernel() {            // block partial sums
    __shared__ int s[256];
    int b = blockIdx.x, G, lb, n;
    const int* cnt;
    if (b < NBA)             { G = 0; lb = b;             n = NN;    cnt = g_cnt_adj; }
    else if (b < NBA + NBT)  { G = 1; lb = b - NBA;       n = MM;    cnt = g_cnt_tag; }
    else                     { G = 2; lb = b - NBA - NBT; n = USERN; cnt = g_cnt_soc; }
    int t = threadIdx.x;
    int i = lb * 256 + t;
    s[t] = (i < n) ? cnt[i] : 0;
    __syncthreads();
    for (int d = 128; d > 0; d >>= 1) {
        if (t < d) s[t] += s[t + d];
        __syncthreads();
    }
    if (t == 0) g_part[G][lb] = s[0];
}

__global__ void scanB_all_kernel() {            // scan partials (block=graph)
    __shared__ int s[1024];
    int G = blockIdx.x;
    int nb = (G == 0) ? NBA : (G == 1) ? NBT : NBS;
    int t = threadIdx.x;
    s[t] = (t < nb) ? g_part[G][t] : 0;
    __syncthreads();
    for (int d = 1; d < 1024; d <<= 1) {
        int v = 0;
        if (t >= d) v = s[t - d];
        __syncthreads();
        if (t >= d) s[t] += v;
        __syncthreads();
    }
    if (t < nb) g_part[G][t] = (t == 0) ? 0 : s[t - 1];  // exclusive
}

__global__ void scanC_all_kernel() {            // final offsets
    __shared__ int s[256];
    int b = blockIdx.x, G, lb, n;
    const int* cnt; int* off; int* cur;
    if (b < NBA)            { G = 0; lb = b;             n = NN;    cnt = g_cnt_adj; off = g_off_adj; cur = g_cur_adj; }
    else if (b < NBA + NBT) { G = 1; lb = b - NBA;       n = MM;    cnt = g_cnt_tag; off = g_off_tag; cur = g_cur_tag; }
    else                    { G = 2; lb = b - NBA - NBT; n = USERN; cnt = g_cnt_soc; off = g_off_soc; cur = g_cur_soc; }
    int t = threadIdx.x;
    int i = lb * 256 + t;
    int c = (i < n) ? cnt[i] : 0;
    s[t] = c;
    __syncthreads();
    for (int d = 1; d < 256; d <<= 1) {
        int v = 0;
        if (t >= d) v = s[t - d];
        __syncthreads();
        if (t >= d) s[t] += v;
        __syncthreads();
    }
    if (i < n) {
        int excl = g_part[G][lb] + s[t] - c;
        off[i] = excl;
        cur[i] = excl;
        if (i == n - 1) off[n] = excl + c;
    }
}

// One launch bins all three graphs. Both layers' dropout weights are computed
// here (bit-exact, per-edge counters shared with the reference), so the gather
// loop is pure memory. Record = (col, w_layer0 bits, w_layer1 bits, 0).
struct Keys { uint32_t k[12]; };  // [layer0: adj,tag,soc][layer1: adj,tag,soc] x (k0,k1)

__global__ void bin_all_kernel(const int* __restrict__ ar, const int* __restrict__ ac,
                               const float* __restrict__ av,
                               const int* __restrict__ tr, const int* __restrict__ tc,
                               const float* __restrict__ tv,
                               const int* __restrict__ sr, const int* __restrict__ sc,
                               const float* __restrict__ sv,
                               Keys K) {
    int t = blockIdx.x * blockDim.x + threadIdx.x;
    if (t < E_ADJ) {
        float v = av[t];
        float w0 = drop_weight(K.k[0], K.k[1], (uint32_t)t, v);
        float w1 = drop_weight(K.k[6], K.k[7], (uint32_t)t, v);
        int pos = atomicAdd(g_cur_adj + ar[t], 1);
        g_ce_adj[pos] = make_int4(ac[t], __float_as_int(w0), __float_as_int(w1), 0);
    } else if (t < E_ADJ + E_TAG) {
        int e = t - E_ADJ;
        float v = tv[e];
        float w0 = drop_weight(K.k[2], K.k[3], (uint32_t)e, v);
        float w1 = drop_weight(K.k[8], K.k[9], (uint32_t)e, v);
        int pos = atomicAdd(g_cur_tag + tr[e], 1);
        g_ce_tag[pos] = make_int4(tc[e], __float_as_int(w0), __float_as_int(w1), 0);
    } else if (t < E_TOT) {
        int e = t - E_ADJ - E_TAG;
        float v = sv[e];
        float w0 = drop_weight(K.k[4], K.k[5], (uint32_t)e, v);
        float w1 = drop_weight(K.k[10], K.k[11], (uint32_t)e, v);
        int pos = atomicAdd(g_cur_soc + sr[e], 1);
        g_ce_soc[pos] = make_int4(sc[e], __float_as_int(w0), __float_as_int(w1), 0);
    }
}

// ---------------- unified gather: one warp per destination row --------------
// Row space: [0,NN) adj->g_tem, [NN,NN+MM) tag->g_tg, [NN+MM,RTOT) soc->g_soc.
// Chunked: lane loads its own record (precomputed weight), then 32 broadcast
// iterations each doing one independent coalesced 256B row read + FMA.
template <int L>
__global__ void gather_all_kernel() {
    int gw = (blockIdx.x * blockDim.x + threadIdx.x) >> 5;
    int lane = threadIdx.x & 31;
    if (gw >= RTOT) return;
    const int* off; const int4* ce; float* dst; bool isTag = false;
    int r;
    if (gw < NN) {
        r = gw;           off = g_off_adj; ce = g_ce_adj; dst = g_tem + (size_t)r * DD;
    } else if (gw < NN + MM) {
        r = gw - NN;      off = g_off_tag; ce = g_ce_tag; dst = g_tg + (size_t)r * DD;
        isTag = true;
    } else {
        r = gw - NN - MM; off = g_off_soc; ce = g_ce_soc; dst = g_soc + (size_t)r * DD;
    }
    const float2* lat2 = reinterpret_cast<const float2*>(g_lat);
    const float2* tl2  = reinterpret_cast<const float2*>(g_taglat);

    int beg = off[r];
    int end = off[r + 1];
    float2 acc = make_float2(0.f, 0.f);
    for (int base = beg; base < end; base += 32) {
        int m = end - base; if (m > 32) m = 32;
        int col = 0;
        float wgt = 0.f;
        if (lane < m) {
            int4 c = __ldg(ce + base + lane);
            col = c.x;
            wgt = __int_as_float((L == 0) ? c.y : c.z);
        }
        #pragma unroll 4
        for (int j = 0; j < m; ++j) {
            float we = __shfl_sync(0xffffffffu, wgt, j);
            int cc = __shfl_sync(0xffffffffu, col, j);
            if (we != 0.f) {
                const float2* s;
                if (isTag) {
                    s = (cc < ITEMN) ? lat2 + (size_t)(USERN + cc) * Q2
                                     : tl2 + (size_t)cc * Q2;
                } else {
                    s = lat2 + (size_t)cc * Q2;
                }
                float2 v = s[lane];
                acc.x += we * v.x;
                acc.y += we * v.y;
            }
        }
    }
    reinterpret_cast<float2*>(dst)[lane] = acc;
}

// ---------------- combine ---------------------------------------------------
__device__ __forceinline__ float lk(float x) { return x >= 0.f ? x : 0.5f * x; }
__device__ __forceinline__ float4 lk4(float4 h) {
    return make_float4(lk(h.x), lk(h.y), lk(h.z), lk(h.w));
}

// LeakyReLU + merge + acc update. Row-sum buffers are plain-overwritten by the
// next layer's gathers, so nothing is zeroed.
__global__ void combine_kernel(float4* __restrict__ out) {
    int t = blockIdx.x * blockDim.x + threadIdx.x;
    if (t < NN * Q4) {
        float4 h = reinterpret_cast<float4*>(g_tem)[t];
        float4 o = lk4(h);
        if (t < USERN * Q4) {
            float4 s = lk4(reinterpret_cast<float4*>(g_soc)[t]);
            o.x += s.x; o.y += s.y; o.z += s.z; o.w += s.w;
        } else {
            float4 g = lk4(reinterpret_cast<float4*>(g_tg)[t - USERN * Q4]);
            o.x += g.x; o.y += g.y; o.z += g.z; o.w += g.w;
        }
        reinterpret_cast<float4*>(g_lat)[t] = o;
        float4 a = out[t];
        out[t] = make_float4(a.x + o.x, a.y + o.y, a.z + o.z, a.w + o.w);
    }
    if (t < MM * Q4) {
        reinterpret_cast<float4*>(g_taglat)[t] =
            lk4(reinterpret_cast<float4*>(g_tg)[t]);
    }
}

// ---------------- launch ----------------------------------------------------
extern "C" void kernel_launch(void* const* d_in, const int* in_sizes, int n_in,
                              void* d_out, int out_size) {
    const float4* uE   = (const float4*)d_in[0];
    const float4* iE   = (const float4*)d_in[1];
    const float4* tE   = (const float4*)d_in[2];
    const int*   adj_r = (const int*)d_in[3];
    const int*   adj_c = (const int*)d_in[4];
    const float* adj_v = (const float*)d_in[5];
    const int*   tag_r = (const int*)d_in[6];
    const int*   tag_c = (const int*)d_in[7];
    const float* tag_v = (const float*)d_in[8];
    const int*   soc_r = (const int*)d_in[9];
    const int*   soc_c = (const int*)d_in[10];
    const float* soc_v = (const float*)d_in[11];
    float4* out = (float4*)d_out;

    const int T = 256;
    auto cdiv = [](long long a, long long b) { return (int)((a + b - 1) / b); };

    // Fold dropout keys on the host: key(42) = (0, 42); fold_in(key, d) =
    // threefry_2x32(key, (0, d)). fold_in is NOT affected by the
    // threefry_partitionable flag — only random_bits is.
    Keys K;
    for (int L = 0; L < 2; ++L)
        for (int g = 0; g < 3; ++g) {
            uint32_t a, b;
            tf2x32(0u, 42u, 0u, (uint32_t)(3 * L + g), a, b);
            K.k[L * 6 + g * 2]     = a;
            K.k[L * 6 + g * 2 + 1] = b;
        }

    init_kernel<<<cdiv((long long)NN * Q4, T), T>>>(uE, iE, tE, out);
    hist_all_kernel<<<cdiv(E_TOT, T), T>>>(adj_r, tag_r, soc_r);
    scanA_all_kernel<<<NBA + NBT + NBS, 256>>>();
    scanB_all_kernel<<<3, 1024>>>();
    scanC_all_kernel<<<NBA + NBT + NBS, 256>>>();
    bin_all_kernel<<<cdiv(E_TOT, T), T>>>(adj_r, adj_c, adj_v,
                                          tag_r, tag_c, tag_v,
                                          soc_r, soc_c, soc_v, K);

    gather_all_kernel<0><<<cdiv((long long)RTOT * 32, T), T>>>();
    combine_kernel<<<cdiv((long long)NN * Q4, T), T>>>(out);
    gather_all_kernel<1><<<cdiv((long long)RTOT * 32, T), T>>>();
    combine_kernel<<<cdiv((long long)NN * Q4, T), T>>>(out);
}

// round 17
// speedup vs baseline: 1.0218x; 1.0218x over previous
#include <cuda_runtime.h>
#include <cstdint>

// ---------------- problem constants ----------------
#define USERN 100000
#define ITEMN 50000
#define TAGN  20000
#define NN (USERN + ITEMN)   // 150000 interaction-graph nodes
#define MM (ITEMN + TAGN)    // 70000 tag-graph nodes
#define RTOT (NN + MM + USERN)  // 320000 unified gather rows
#define DD 64
#define Q4 16                // float4 per embedding row
#define Q2 32                // float2 per embedding row
#define E_ADJ 2000000
#define E_TAG 1000000
#define E_SOC 1000000
#define E_TOT (E_ADJ + E_TAG + E_SOC)

// scan block counts (256 threads/block)
#define NBA ((NN + 255) / 256)      // 586
#define NBT ((MM + 255) / 256)      // 274
#define NBS ((USERN + 255) / 256)   // 391

// ---------------- device scratch (no allocs allowed) ----------------
__device__ float g_lat[NN * DD];
__device__ float g_taglat[MM * DD];
__device__ float g_tem[NN * DD];     // adj-graph row sums (gather output)
__device__ float g_tg[MM * DD];      // tag-graph row sums
__device__ float g_soc[USERN * DD];  // social-graph row sums

// CSR scratch (structure constant across layers; built once per call)
__device__ int g_cnt_adj[NN];
__device__ int g_off_adj[NN + 1];
__device__ int g_cur_adj[NN];
__device__ int g_cnt_tag[MM];
__device__ int g_off_tag[MM + 1];
__device__ int g_cur_tag[MM];
__device__ int g_cnt_soc[USERN];
__device__ int g_off_soc[USERN + 1];
__device__ int g_cur_soc[USERN];
__device__ int g_part[3][1024];      // raw block sums from scanA
// Packed edge record: x = col | mask0<<18 | mask1<<19 ; y = val bits
__device__ int2 g_ce_adj[E_ADJ];
__device__ int2 g_ce_tag[E_TAG];
__device__ int2 g_ce_soc[E_SOC];

// ---------------- threefry-2x32 (exact JAX implementation) ----------------
__host__ __device__ __forceinline__ void tf2x32(uint32_t k0, uint32_t k1,
                                                uint32_t x0, uint32_t x1,
                                                uint32_t& o0, uint32_t& o1) {
    uint32_t ks2 = k0 ^ k1 ^ 0x1BD11BDAu;
    x0 += k0; x1 += k1;
#define TF_RR(r) { x0 += x1; x1 = (x1 << (r)) | (x1 >> (32 - (r))); x1 ^= x0; }
    TF_RR(13) TF_RR(15) TF_RR(26) TF_RR(6)   x0 += k1;  x1 += ks2 + 1u;
    TF_RR(17) TF_RR(29) TF_RR(16) TF_RR(24)  x0 += ks2; x1 += k0 + 2u;
    TF_RR(13) TF_RR(15) TF_RR(26) TF_RR(6)   x0 += k0;  x1 += k1 + 3u;
    TF_RR(17) TF_RR(29) TF_RR(16) TF_RR(24)  x0 += k1;  x1 += ks2 + 4u;
    TF_RR(13) TF_RR(15) TF_RR(26) TF_RR(6)   x0 += ks2; x1 += k0 + 5u;
#undef TF_RR
    o0 = x0; o1 = x1;
}

// Bit-exact JAX dropout mask bit (partitionable threefry: bits = xor-fold of
// threefry2x32(key, 0, e)); mask = floor(u + KEEP) in {0,1}.
__device__ __forceinline__ uint32_t drop_mask(uint32_t k0, uint32_t k1, uint32_t e) {
    uint32_t o0, o1;
    tf2x32(k0, k1, 0u, e, o0, o1);
    uint32_t bits = o0 ^ o1;
    float u = __uint_as_float((bits >> 9) | 0x3f800000u) - 1.0f;
    return (floorf(u + 0.9f) != 0.0f) ? 1u : 0u;
}

// ---------------- init: embeddings + acc seed + CSR count zeroing ----------
__global__ void init_kernel(const float4* __restrict__ uE,
                            const float4* __restrict__ iE,
                            const float4* __restrict__ tE,
                            float4* __restrict__ out) {
    int t = blockIdx.x * blockDim.x + threadIdx.x;
    if (t < NN * Q4) {
        float4 v = (t < USERN * Q4) ? uE[t] : iE[t - USERN * Q4];
        reinterpret_cast<float4*>(g_lat)[t] = v;
        out[t] = v;                                    // acc starts at lat
    }
    if (t < MM * Q4) {
        float4 v = (t < ITEMN * Q4) ? iE[t] : tE[t - ITEMN * Q4];
        reinterpret_cast<float4*>(g_taglat)[t] = v;
    }
    if (t < NN) g_cnt_adj[t] = 0;
    if (t < MM) g_cnt_tag[t] = 0;
    if (t < USERN) g_cnt_soc[t] = 0;
}

// ---------------- CSR build (once per call) --------------------------------
__global__ void hist_all_kernel(const int* __restrict__ ar,
                                const int* __restrict__ tr,
                                const int* __restrict__ sr) {
    int t = blockIdx.x * blockDim.x + threadIdx.x;
    if (t < E_ADJ)              atomicAdd(g_cnt_adj + ar[t], 1);
    else if (t < E_ADJ + E_TAG) atomicAdd(g_cnt_tag + tr[t - E_ADJ], 1);
    else if (t < E_TOT)         atomicAdd(g_cnt_soc + sr[t - E_ADJ - E_TAG], 1);
}

// Pass A: per-block raw sums of counts.
__global__ void scanA_all_kernel() {
    __shared__ int s[256];
    int b = blockIdx.x, G, lb, n;
    const int* cnt;
    if (b < NBA)             { G = 0; lb = b;             n = NN;    cnt = g_cnt_adj; }
    else if (b < NBA + NBT)  { G = 1; lb = b - NBA;       n = MM;    cnt = g_cnt_tag; }
    else                     { G = 2; lb = b - NBA - NBT; n = USERN; cnt = g_cnt_soc; }
    int t = threadIdx.x;
    int i = lb * 256 + t;
    s[t] = (i < n) ? cnt[i] : 0;
    __syncthreads();
    for (int d = 128; d > 0; d >>= 1) {
        if (t < d) s[t] += s[t + d];
        __syncthreads();
    }
    if (t == 0) g_part[G][lb] = s[0];
}

// Pass C (fused with the partials scan): each block reduces g_part[G][0..lb)
// itself, then does the local exclusive scan and writes final offsets.
__global__ void scanC_all_kernel() {
    __shared__ int s[256];
    __shared__ int p[256];
    int b = blockIdx.x, G, lb, n;
    const int* cnt; int* off; int* cur;
    if (b < NBA)            { G = 0; lb = b;             n = NN;    cnt = g_cnt_adj; off = g_off_adj; cur = g_cur_adj; }
    else if (b < NBA + NBT) { G = 1; lb = b - NBA;       n = MM;    cnt = g_cnt_tag; off = g_off_tag; cur = g_cur_tag; }
    else                    { G = 2; lb = b - NBA - NBT; n = USERN; cnt = g_cnt_soc; off = g_off_soc; cur = g_cur_soc; }
    int t = threadIdx.x;
    // base = sum of raw block sums before this block
    int acc = 0;
    for (int i = t; i < lb; i += 256) acc += g_part[G][i];
    p[t] = acc;
    __syncthreads();
    for (int d = 128; d > 0; d >>= 1) {
        if (t < d) p[t] += p[t + d];
        __syncthreads();
    }
    int base = p[0];
    // local inclusive scan of this block's counts
    int i = lb * 256 + t;
    int c = (i < n) ? cnt[i] : 0;
    s[t] = c;
    __syncthreads();
    for (int d = 1; d < 256; d <<= 1) {
        int v = 0;
        if (t >= d) v = s[t - d];
        __syncthreads();
        if (t >= d) s[t] += v;
        __syncthreads();
    }
    if (i < n) {
        int excl = base + s[t] - c;
        off[i] = excl;
        cur[i] = excl;
        if (i == n - 1) off[n] = excl + c;
    }
}

// One launch bins all three graphs. Both layers' dropout MASK BITS are baked
// into the record (bit-exact threefry, per-edge counters matching the
// reference); the value is stored raw. Record = (col|m0<<18|m1<<19, val bits).
struct Keys { uint32_t k[12]; };  // [layer0: adj,tag,soc][layer1: adj,tag,soc] x (k0,k1)

__global__ void bin_all_kernel(const int* __restrict__ ar, const int* __restrict__ ac,
                               const float* __restrict__ av,
                               const int* __restrict__ tr, const int* __restrict__ tc,
                               const float* __restrict__ tv,
                               const int* __restrict__ sr, const int* __restrict__ sc,
                               const float* __restrict__ sv,
                               Keys K) {
    int t = blockIdx.x * blockDim.x + threadIdx.x;
    if (t < E_ADJ) {
        uint32_t m0 = drop_mask(K.k[0], K.k[1], (uint32_t)t);
        uint32_t m1 = drop_mask(K.k[6], K.k[7], (uint32_t)t);
        int pos = atomicAdd(g_cur_adj + ar[t], 1);
        g_ce_adj[pos] = make_int2((int)((uint32_t)ac[t] | (m0 << 18) | (m1 << 19)),
                                  __float_as_int(av[t]));
    } else if (t < E_ADJ + E_TAG) {
        int e = t - E_ADJ;
        uint32_t m0 = drop_mask(K.k[2], K.k[3], (uint32_t)e);
        uint32_t m1 = drop_mask(K.k[8], K.k[9], (uint32_t)e);
        int pos = atomicAdd(g_cur_tag + tr[e], 1);
        g_ce_tag[pos] = make_int2((int)((uint32_t)tc[e] | (m0 << 18) | (m1 << 19)),
                                  __float_as_int(tv[e]));
    } else if (t < E_TOT) {
        int e = t - E_ADJ - E_TAG;
        uint32_t m0 = drop_mask(K.k[4], K.k[5], (uint32_t)e);
        uint32_t m1 = drop_mask(K.k[10], K.k[11], (uint32_t)e);
        int pos = atomicAdd(g_cur_soc + sr[e], 1);
        g_ce_soc[pos] = make_int2((int)((uint32_t)sc[e] | (m0 << 18) | (m1 << 19)),
                                  __float_as_int(sv[e]));
    }
}

// ---------------- unified gather: one warp per destination row --------------
// Row space: [0,NN) adj->g_tem, [NN,NN+MM) tag->g_tg, [NN+MM,RTOT) soc->g_soc.
// Chunked: lane loads its own packed record, reconstructs the layer weight
// (kept edge: w = val * (1/KEEP), bit-exact vs (val*mask)*(1/KEEP)), then 32
// broadcast iterations each doing one independent coalesced 256B row read+FMA.
template <int L>
__global__ void gather_all_kernel() {
    int gw = (blockIdx.x * blockDim.x + threadIdx.x) >> 5;
    int lane = threadIdx.x & 31;
    if (gw >= RTOT) return;
    const int* off; const int2* ce; float* dst; bool isTag = false;
    int r;
    if (gw < NN) {
        r = gw;           off = g_off_adj; ce = g_ce_adj; dst = g_tem + (size_t)r * DD;
    } else if (gw < NN + MM) {
        r = gw - NN;      off = g_off_tag; ce = g_ce_tag; dst = g_tg + (size_t)r * DD;
        isTag = true;
    } else {
        r = gw - NN - MM; off = g_off_soc; ce = g_ce_soc; dst = g_soc + (size_t)r * DD;
    }
    const float2* lat2 = reinterpret_cast<const float2*>(g_lat);
    const float2* tl2  = reinterpret_cast<const float2*>(g_taglat);
    const float INVKEEP = (float)(1.0 / 0.9);

    int beg = off[r];
    int end = off[r + 1];
    float2 acc = make_float2(0.f, 0.f);
    for (int base = beg; base < end; base += 32) {
        int m = end - base; if (m > 32) m = 32;
        int col = 0;
        float wgt = 0.f;
        if (lane < m) {
            int2 c = __ldg(ce + base + lane);
            uint32_t cx = (uint32_t)c.x;
            col = (int)(cx & 0x3FFFFu);
            uint32_t keep = (cx >> (18 + L)) & 1u;
            wgt = keep ? __int_as_float(c.y) * INVKEEP : 0.f;
        }
        #pragma unroll 4
        for (int j = 0; j < m; ++j) {
            float we = __shfl_sync(0xffffffffu, wgt, j);
            int cc = __shfl_sync(0xffffffffu, col, j);
            if (we != 0.f) {
                const float2* s;
                if (isTag) {
                    s = (cc < ITEMN) ? lat2 + (size_t)(USERN + cc) * Q2
                                     : tl2 + (size_t)cc * Q2;
                } else {
                    s = lat2 + (size_t)cc * Q2;
                }
                float2 v = s[lane];
                acc.x += we * v.x;
                acc.y += we * v.y;
            }
        }
    }
    reinterpret_cast<float2*>(dst)[lane] = acc;
}

// ---------------- combine ---------------------------------------------------
__device__ __forceinline__ float lk(float x) { return x >= 0.f ? x : 0.5f * x; }
__device__ __forceinline__ float4 lk4(float4 h) {
    return make_float4(lk(h.x), lk(h.y), lk(h.z), lk(h.w));
}

// LeakyReLU + merge + acc update. Row-sum buffers are plain-overwritten by the
// next layer's gathers, so nothing is zeroed.
__global__ void combine_kernel(float4* __restrict__ out) {
    int t = blockIdx.x * blockDim.x + threadIdx.x;
    if (t < NN * Q4) {
        float4 h = reinterpret_cast<float4*>(g_tem)[t];
        float4 o = lk4(h);
        if (t < USERN * Q4) {
            float4 s = lk4(reinterpret_cast<float4*>(g_soc)[t]);
            o.x += s.x; o.y += s.y; o.z += s.z; o.w += s.w;
        } else {
            float4 g = lk4(reinterpret_cast<float4*>(g_tg)[t - USERN * Q4]);
            o.x += g.x; o.y += g.y; o.z += g.z; o.w += g.w;
        }
        reinterpret_cast<float4*>(g_lat)[t] = o;
        float4 a = out[t];
        out[t] = make_float4(a.x + o.x, a.y + o.y, a.z + o.z, a.w + o.w);
    }
    if (t < MM * Q4) {
        reinterpret_cast<float4*>(g_taglat)[t] =
            lk4(reinterpret_cast<float4*>(g_tg)[t]);
    }
}

// ---------------- launch ----------------------------------------------------
extern "C" void kernel_launch(void* const* d_in, const int* in_sizes, int n_in,
                              void* d_out, int out_size) {
    const float4* uE   = (const float4*)d_in[0];
    const float4* iE   = (const float4*)d_in[1];
    const float4* tE   = (const float4*)d_in[2];
    const int*   adj_r = (const int*)d_in[3];
    const int*   adj_c = (const int*)d_in[4];
    const float* adj_v = (const float*)d_in[5];
    const int*   tag_r = (const int*)d_in[6];
    const int*   tag_c = (const int*)d_in[7];
    const float* tag_v = (const float*)d_in[8];
    const int*   soc_r = (const int*)d_in[9];
    const int*   soc_c = (const int*)d_in[10];
    const float* soc_v = (const float*)d_in[11];
    float4* out = (float4*)d_out;

    const int T = 256;
    auto cdiv = [](long long a, long long b) { return (int)((a + b - 1) / b); };

    // Fold dropout keys on the host: key(42) = (0, 42); fold_in(key, d) =
    // threefry_2x32(key, (0, d)). fold_in is NOT affected by the
    // threefry_partitionable flag — only random_bits is.
    Keys K;
    for (int L = 0; L < 2; ++L)
        for (int g = 0; g < 3; ++g) {
            uint32_t a, b;
            tf2x32(0u, 42u, 0u, (uint32_t)(3 * L + g), a, b);
            K.k[L * 6 + g * 2]     = a;
            K.k[L * 6 + g * 2 + 1] = b;
        }

    // Launch order chosen so gather_all<0> is the 6th launch (ncu -s 5 -c 1
    // capture slot) — we need the hot kernel's profile, not a bystander's.
    init_kernel<<<cdiv((long long)NN * Q4, T), T>>>(uE, iE, tE, out);
    hist_all_kernel<<<cdiv(E_TOT, T), T>>>(adj_r, tag_r, soc_r);
    scanA_all_kernel<<<NBA + NBT + NBS, 256>>>();
    scanC_all_kernel<<<NBA + NBT + NBS, 256>>>();
    bin_all_kernel<<<cdiv(E_TOT, T), T>>>(adj_r, adj_c, adj_v,
                                          tag_r, tag_c, tag_v,
                                          soc_r, soc_c, soc_v, K);

    gather_all_kernel<0><<<cdiv((long long)RTOT * 32, T), T>>>();
    combine_kernel<<<cdiv((long long)NN * Q4, T), T>>>(out);
    gather_all_kernel<1><<<cdiv((long long)RTOT * 32, T), T>>>();
    combine_kernel<<<cdiv((long long)NN * Q4, T), T>>>(out);
}